// round 14
// baseline (speedup 1.0000x reference)
#include <cuda_runtime.h>
#include <cstdint>

static constexpr int S_LEN   = 8192;
static constexpr int Dh      = 64;
static constexpr int OUTROWS = 7936;   // S - WINDOW/2
static constexpr int TK      = 32;     // keys per tile
static constexpr int PAD     = 68;     // smem row stride (f32 words); 68 % 8 == 4 -> LDSM conflict-free
static constexpr int NT      = 128;    // 4 warps x 16 q-rows = 64 queries per CTA, 3 CTAs/SM

// Truncation-bias compensation (validated R13): V and P enter the tensor core as
// raw f32 -> tf32 truncation, each a coherent 2^-12 shrink on O; l is exact.
static constexpr float LCOMP = 1.00048828125f;   // 1 + 2^-11

__device__ __forceinline__ uint32_t f2tf32(float x) {
    uint32_t r; asm("cvt.rna.tf32.f32 %0, %1;" : "=r"(r) : "f"(x)); return r;
}
__device__ __forceinline__ float ex2f(float x) {
    float r; asm("ex2.approx.ftz.f32 %0, %1;" : "=f"(r) : "f"(x)); return r;
}
__device__ __forceinline__ void mma8(float d[4], const uint32_t a[4], const uint32_t* b) {
    asm("mma.sync.aligned.m16n8k8.row.col.f32.tf32.tf32.f32 "
        "{%0,%1,%2,%3}, {%4,%5,%6,%7}, {%8,%9}, {%0,%1,%2,%3};"
        : "+f"(d[0]), "+f"(d[1]), "+f"(d[2]), "+f"(d[3])
        : "r"(a[0]), "r"(a[1]), "r"(a[2]), "r"(a[3]), "r"(b[0]), "r"(b[1]));
}
__device__ __forceinline__ void ldsm4(uint32_t r[4], uint32_t saddr) {
    asm volatile("ldmatrix.sync.aligned.m8n8.x4.shared.b16 {%0,%1,%2,%3}, [%4];"
                 : "=r"(r[0]), "=r"(r[1]), "=r"(r[2]), "=r"(r[3]) : "r"(saddr));
}
__device__ __forceinline__ void cpa16(uint32_t dst, const void* src) {
    asm volatile("cp.async.cg.shared.global [%0], [%1], 16;" :: "r"(dst), "l"(src));
}

__global__ __launch_bounds__(NT, 3)
void swa_mma(const float* __restrict__ qg, const float* __restrict__ kg,
             const float* __restrict__ vg, float* __restrict__ outg)
{
    __shared__ float kbuf[2][TK * PAD];   // 8.5 KB each
    __shared__ float vbuf[2][TK * PAD];   // swizzled: d' = (d + 32*((key>>1)&1)) & 63

    const int bh = blockIdx.y, qb = blockIdx.x;   // qb: 64-query block
    int kstart, klen;
    if (qb < 4) { kstart = 0; klen = 256; }
    else        { kstart = 256 + 512 * ((qb - 4) >> 3); klen = 512; }
    const int nt = 1 + klen / TK;   // tile 0 = 32 global keys, then local tiles

    const int tid  = threadIdx.x;
    const int warp = tid >> 5, lane = tid & 31;
    const int g = lane >> 2, tig = lane & 3;

    const float C = 0.125f * 1.44269504088896340736f;  // scale * log2(e)
    const size_t kvbase = (size_t)bh * S_LEN * Dh;

    // LDSM lane addressing for K fragments (4 matrices per x4).
    const int krow = ((lane >> 4) << 3) | (lane & 7);   // row within 16-row pair-block
    const int kcol = ((lane >> 3) & 1) * 4;             // d half (0 or 4)

    // V fragment address constants (permuted-A scheme).
    const int cg = g + ((tig & 1) << 5);   // col pre-&63 (adds the swizzle rotation)

    // Per-thread cp.async staging addresses (4 x 16B per matrix per tile).
    int krowj[4], kdst[4], vdst[4];
    #pragma unroll
    for (int j = 0; j < 4; j++) {
        const int f4i = tid + NT * j, row = f4i >> 4, c = f4i & 15;
        krowj[j] = f4i;
        kdst[j] = (row * PAD + c * 4) * 4;
        vdst[j] = (row * PAD + ((4 * c + (((row >> 1) & 1) << 5)) & 63)) * 4;
    }

    // ---- Q fragments (RNA-rounded tf32): [kb=8][4] for this warp's 16 rows ----
    uint32_t qf[8][4];
    {
        const float* qp = qg + kvbase + (size_t)(qb * 64 + warp * 16) * Dh;
        #pragma unroll
        for (int kb = 0; kb < 8; kb++) {
            const int c0 = kb * 8 + tig;
            qf[kb][0] = f2tf32(qp[(g    ) * Dh + c0    ]);
            qf[kb][1] = f2tf32(qp[(g + 8) * Dh + c0    ]);
            qf[kb][2] = f2tf32(qp[(g    ) * Dh + c0 + 4]);
            qf[kb][3] = f2tf32(qp[(g + 8) * Dh + c0 + 4]);
        }
    }

    float o[8][4];
    #pragma unroll
    for (int nb = 0; nb < 8; nb++)
        #pragma unroll
        for (int i = 0; i < 4; i++) o[nb][i] = 0.f;
    float mrow[2] = {-1e30f, -1e30f};
    // Per-thread partial denominators; quad-reduced once at the end.
    float lrow[2] = {0.f, 0.f};

    const float4* kp4 = (const float4*)(kg + kvbase);
    const float4* vp4 = (const float4*)(vg + kvbase);

    const uint32_t ksm0 = (uint32_t)__cvta_generic_to_shared(kbuf[0]);
    const uint32_t ksm1 = (uint32_t)__cvta_generic_to_shared(kbuf[1]);
    const uint32_t vsm0 = (uint32_t)__cvta_generic_to_shared(vbuf[0]);
    const uint32_t vsm1 = (uint32_t)__cvta_generic_to_shared(vbuf[1]);

    // Prologue: async-stage tile 0 (32 global keys).
    {
        #pragma unroll
        for (int j = 0; j < 4; j++) {
            cpa16(ksm0 + kdst[j], kp4 + krowj[j]);
            cpa16(vsm0 + vdst[j], vp4 + krowj[j]);
        }
        asm volatile("cp.async.commit_group;");
        asm volatile("cp.async.wait_group 0;" ::: "memory");
    }
    __syncthreads();

    for (int t = 0; t < nt; t++) {
        const bool pf = (t + 1) < nt;
        const int cur = t & 1;
        const uint32_t ks = cur ? ksm1 : ksm0;
        const uint32_t vs = cur ? vsm1 : vsm0;
        const uint32_t ksn = cur ? ksm0 : ksm1;
        const uint32_t vsn = cur ? vsm0 : vsm1;

        // Async-prefetch next tile straight into the other smem buffer.
        if (pf) {
            const size_t roff = (size_t)(kstart + t * TK) * (Dh / 4);
            #pragma unroll
            for (int j = 0; j < 4; j++) {
                cpa16(ksn + kdst[j], kp4 + roff + krowj[j]);
                cpa16(vsn + vdst[j], vp4 + roff + krowj[j]);
            }
            asm volatile("cp.async.commit_group;");
        }

        // ---- S = Q K^T (K frags via ldmatrix.x4, conflict-free) ----
        float sf[4][4];
        #pragma unroll
        for (int nb = 0; nb < 4; nb++)
            #pragma unroll
            for (int i = 0; i < 4; i++) sf[nb][i] = 0.f;
        #pragma unroll
        for (int kb = 0; kb < 8; kb++) {
            #pragma unroll
            for (int p = 0; p < 2; p++) {
                uint32_t kf[4];
                const uint32_t a = ks + (uint32_t)(((p * 16 + krow) * PAD + kb * 8 + kcol) * 4);
                ldsm4(kf, a);
                mma8(sf[2 * p],     qf[kb], kf);
                mma8(sf[2 * p + 1], qf[kb], kf + 2);
            }
        }

        // ---- online softmax (P left as raw f32; tensor core truncates) ----
        {
            float r0 = -1e30f, r1 = -1e30f;
            #pragma unroll
            for (int nb = 0; nb < 4; nb++) {
                r0 = fmaxf(r0, fmaxf(sf[nb][0], sf[nb][1]));
                r1 = fmaxf(r1, fmaxf(sf[nb][2], sf[nb][3]));
            }
            r0 = fmaxf(r0, __shfl_xor_sync(0xffffffffu, r0, 1));
            r0 = fmaxf(r0, __shfl_xor_sync(0xffffffffu, r0, 2));
            r1 = fmaxf(r1, __shfl_xor_sync(0xffffffffu, r1, 1));
            r1 = fmaxf(r1, __shfl_xor_sync(0xffffffffu, r1, 2));
            const float mn0 = fmaxf(mrow[0], r0);
            const float mn1 = fmaxf(mrow[1], r1);
            const float al0 = ex2f((mrow[0] - mn0) * C);
            const float al1 = ex2f((mrow[1] - mn1) * C);
            mrow[0] = mn0; mrow[1] = mn1;
            const float mb0 = mn0 * C, mb1 = mn1 * C;
            float s0 = 0.f, s1 = 0.f;
            #pragma unroll
            for (int nb = 0; nb < 4; nb++) {
                float p0 = ex2f(fmaf(sf[nb][0], C, -mb0));
                float p1 = ex2f(fmaf(sf[nb][1], C, -mb0));
                float p2 = ex2f(fmaf(sf[nb][2], C, -mb1));
                float p3 = ex2f(fmaf(sf[nb][3], C, -mb1));
                s0 += p0 + p1; s1 += p2 + p3;
                sf[nb][0] = p0;
                sf[nb][1] = p1;
                sf[nb][2] = p2;
                sf[nb][3] = p3;
            }
            lrow[0] = lrow[0] * al0 + s0;
            lrow[1] = lrow[1] * al1 + s1;
            #pragma unroll
            for (int nb = 0; nb < 8; nb++) {
                o[nb][0] *= al0; o[nb][1] *= al0;
                o[nb][2] *= al1; o[nb][3] *= al1;
            }
        }

        // ---- O += P V ----
        // Permuted-A: A-frag column c holds key 2c (c<4) / 2(c-4)+1 (c>=4); the S
        // C-fragment registers ARE the A-fragment ({c0,c2,c1,c3}) with zero data
        // movement; B-frag compensates by fetching V rows 8kb+2*tig and 8kb+2*tig+1.
        #pragma unroll
        for (int kb = 0; kb < 4; kb++) {
            const uint32_t a0[4] = { __float_as_uint(sf[kb][0]), __float_as_uint(sf[kb][2]),
                                     __float_as_uint(sf[kb][1]), __float_as_uint(sf[kb][3]) };
            const uint32_t rowbase = vs + (uint32_t)(((kb * 8 + 2 * tig) * PAD) * 4);
            #pragma unroll
            for (int nb = 0; nb < 8; nb++) {
                const uint32_t coff = (uint32_t)(((nb * 8 + cg) & 63) * 4);
                uint32_t b[2];
                asm volatile("ld.shared.b32 %0, [%1];" : "=r"(b[0]) : "r"(rowbase + coff));
                asm volatile("ld.shared.b32 %0, [%1];" : "=r"(b[1]) : "r"(rowbase + PAD * 4 + coff));
                mma8(o[nb], a0, b);
            }
        }

        // Tile boundary: wait for the async prefetch, then flip.
        if (pf) {
            asm volatile("cp.async.wait_group 0;" ::: "memory");
            __syncthreads();
        }
    }

    // ---- final l reduction + bias-compensated normalize + store ----
    {
        float l0 = lrow[0], l1 = lrow[1];
        l0 += __shfl_xor_sync(0xffffffffu, l0, 1);
        l0 += __shfl_xor_sync(0xffffffffu, l0, 2);
        l1 += __shfl_xor_sync(0xffffffffu, l1, 1);
        l1 += __shfl_xor_sync(0xffffffffu, l1, 2);
        const float inv0 = LCOMP / l0;
        const float inv1 = LCOMP / l1;
        const int row0 = qb * 64 + warp * 16 + g;
        float* op0 = outg + ((size_t)bh * OUTROWS + row0) * Dh;
        float* op1 = op0 + 8 * Dh;
        #pragma unroll
        for (int nb = 0; nb < 8; nb++) {
            const int col = nb * 8 + 2 * tig;
            float2 v0 = { o[nb][0] * inv0, o[nb][1] * inv0 };
            *(float2*)(op0 + col) = v0;
            float2 v1 = { o[nb][2] * inv1, o[nb][3] * inv1 };
            *(float2*)(op1 + col) = v1;
        }
    }
}

extern "C" void kernel_launch(void* const* d_in, const int* in_sizes, int n_in,
                              void* d_out, int out_size)
{
    const float* q = (const float*)d_in[0];
    const float* k = (const float*)d_in[1];
    const float* v = (const float*)d_in[2];
    float* out = (float*)d_out;

    dim3 grid(124, 32);   // 124 q-blocks of 64 rows x 32 (b,h)
    swa_mma<<<grid, NT>>>(q, k, v, out);
}

// round 15
// speedup vs baseline: 1.1179x; 1.1179x over previous
#include <cuda_runtime.h>
#include <cstdint>

static constexpr int S_LEN   = 8192;
static constexpr int Dh      = 64;
static constexpr int OUTROWS = 7936;   // S - WINDOW/2
static constexpr int TK      = 32;     // keys per tile
static constexpr int NT      = 128;    // 4 warps x 32 q-rows, 2 CTAs/SM

// f16 smem tiles: 32 keys x 64 f16 = 128 B/row, SW128 swizzle o' = o ^ ((row&7)<<4).

__device__ __forceinline__ float ex2f(float x) {
    float r; asm("ex2.approx.ftz.f32 %0, %1;" : "=f"(r) : "f"(x)); return r;
}
// pack two f32 -> f16x2 (RN, unbiased): lo half = first arg.
__device__ __forceinline__ uint32_t packh(float lo, float hi) {
    uint32_t r; asm("cvt.rn.f16x2.f32 %0, %1, %2;" : "=r"(r) : "f"(hi), "f"(lo)); return r;
}
__device__ __forceinline__ void mmaf16(float d[4], const uint32_t a[4], const uint32_t* b) {
    asm("mma.sync.aligned.m16n8k16.row.col.f32.f16.f16.f32 "
        "{%0,%1,%2,%3}, {%4,%5,%6,%7}, {%8,%9}, {%0,%1,%2,%3};"
        : "+f"(d[0]), "+f"(d[1]), "+f"(d[2]), "+f"(d[3])
        : "r"(a[0]), "r"(a[1]), "r"(a[2]), "r"(a[3]), "r"(b[0]), "r"(b[1]));
}
__device__ __forceinline__ void ldsm4(uint32_t r[4], uint32_t saddr) {
    asm volatile("ldmatrix.sync.aligned.m8n8.x4.shared.b16 {%0,%1,%2,%3}, [%4];"
                 : "=r"(r[0]), "=r"(r[1]), "=r"(r[2]), "=r"(r[3]) : "r"(saddr));
}
__device__ __forceinline__ void ldsm4t(uint32_t r[4], uint32_t saddr) {
    asm volatile("ldmatrix.sync.aligned.m8n8.x4.trans.shared.b16 {%0,%1,%2,%3}, [%4];"
                 : "=r"(r[0]), "=r"(r[1]), "=r"(r[2]), "=r"(r[3]) : "r"(saddr));
}
__device__ __forceinline__ void sts128(uint32_t addr, uint32_t a, uint32_t b, uint32_t c, uint32_t d) {
    asm volatile("st.shared.v4.b32 [%0], {%1,%2,%3,%4};" :: "r"(addr), "r"(a), "r"(b), "r"(c), "r"(d));
}

__global__ __launch_bounds__(NT, 2)
void swa_mma(const float* __restrict__ qg, const float* __restrict__ kg,
             const float* __restrict__ vg, float* __restrict__ outg)
{
    __shared__ __align__(16) char kbuf[2][TK * 128];   // 4 KB each, f16 [key][d]
    __shared__ __align__(16) char vbuf[2][TK * 128];   // 4 KB each, f16 [key][d]

    const int bh = blockIdx.y, qb = blockIdx.x;
    int kstart, klen;
    if (qb < 2) { kstart = 0; klen = 256; }
    else        { kstart = 256 + 512 * ((qb - 2) >> 2); klen = 512; }
    const int nt = 1 + klen / TK;   // tile 0 = 32 global keys, then local tiles

    const int tid  = threadIdx.x;
    const int warp = tid >> 5, lane = tid & 31;
    const int g = lane >> 2, tig = lane & 3;

    const float C = 0.125f * 1.44269504088896340736f;  // scale * log2(e)
    const size_t kvbase = (size_t)bh * S_LEN * Dh;

    // ldmatrix lane constants.
    // K frags (non-trans): matrix m = lane>>3, row in matrix = lane&7.
    const int kxor  = (lane & 7) << 4;                 // swizzle xor (row&7)
    const int kbase = ((lane >> 4) << 3) + (lane & 7); // key within 16-key group (m0,m1 lo; m2,m3 hi)
    const int ksel  = ((lane >> 3) & 1) << 4;          // d half select (m1,m3)
    // V frags (trans): m0,m1 = key halves of 16-key chunk; m2,m3 = next d-block.
    const int vbase = (((lane >> 3) & 1) << 3) + (lane & 7);  // key within chunk
    const int vsel  = ((lane >> 4) & 1) << 4;                 // d-block select

    // Staging: thread -> key row skey, d-quad sq4 (16 f32 = 32 B f16).
    const int skey = tid >> 2, sq4 = tid & 3;
    const int sgm  = skey * 16 + sq4 * 4;                       // float4 index in tile
    const uint32_t sts0 = skey * 128 + ((sq4 * 32)      ^ ((skey & 7) << 4));
    const uint32_t sts1 = skey * 128 + ((sq4 * 32 + 16) ^ ((skey & 7) << 4));

    // ---- Q fragments (RN f16): qf[kc=4][rb=2][4] ----
    uint32_t qf[4][2][4];
    {
        const float* qp = qg + kvbase + (size_t)(qb * 128 + warp * 32) * Dh;
        #pragma unroll
        for (int kc = 0; kc < 4; kc++)
            #pragma unroll
            for (int rb = 0; rb < 2; rb++) {
                const int r0 = rb * 16 + g;
                const int c0 = kc * 16 + 2 * tig;
                qf[kc][rb][0] = packh(qp[(r0    ) * Dh + c0    ], qp[(r0    ) * Dh + c0 + 1]);
                qf[kc][rb][1] = packh(qp[(r0 + 8) * Dh + c0    ], qp[(r0 + 8) * Dh + c0 + 1]);
                qf[kc][rb][2] = packh(qp[(r0    ) * Dh + c0 + 8], qp[(r0    ) * Dh + c0 + 9]);
                qf[kc][rb][3] = packh(qp[(r0 + 8) * Dh + c0 + 8], qp[(r0 + 8) * Dh + c0 + 9]);
            }
    }

    float o[2][8][4];
    #pragma unroll
    for (int rb = 0; rb < 2; rb++)
        #pragma unroll
        for (int nb = 0; nb < 8; nb++)
            #pragma unroll
            for (int i = 0; i < 4; i++) o[rb][nb][i] = 0.f;
    float mrow[2][2] = {{-1e30f, -1e30f}, {-1e30f, -1e30f}};
    float lrow[2][2] = {{0.f, 0.f}, {0.f, 0.f}};

    const float4* kp4 = (const float4*)(kg + kvbase);
    const float4* vp4 = (const float4*)(vg + kvbase);
    float4 stk[4], stv[4];

    const uint32_t ksm0 = (uint32_t)__cvta_generic_to_shared(kbuf[0]);
    const uint32_t ksm1 = (uint32_t)__cvta_generic_to_shared(kbuf[1]);
    const uint32_t vsm0 = (uint32_t)__cvta_generic_to_shared(vbuf[0]);
    const uint32_t vsm1 = (uint32_t)__cvta_generic_to_shared(vbuf[1]);

    // Convert 4 staged float4 (16 f32) -> 8 f16x2 and store 32 B at sts0/sts1.
    auto drain = [&](const float4* st, uint32_t smbase) {
        uint32_t h[8];
        #pragma unroll
        for (int i = 0; i < 4; i++) {
            h[2 * i]     = packh(st[i].x, st[i].y);
            h[2 * i + 1] = packh(st[i].z, st[i].w);
        }
        sts128(smbase + sts0, h[0], h[1], h[2], h[3]);
        sts128(smbase + sts1, h[4], h[5], h[6], h[7]);
    };

    // Prologue: stage tile 0 (32 global keys).
    {
        #pragma unroll
        for (int i = 0; i < 4; i++) { stk[i] = kp4[sgm + i]; stv[i] = vp4[sgm + i]; }
        drain(stk, ksm0);
        drain(stv, vsm0);
    }
    __syncthreads();

    for (int t = 0; t < nt; t++) {
        const bool pf = (t + 1) < nt;
        const int cur = t & 1;
        const uint32_t ks = cur ? ksm1 : ksm0;
        const uint32_t vs = cur ? vsm1 : vsm0;
        const uint32_t ksn = cur ? ksm0 : ksm1;
        const uint32_t vsn = cur ? vsm0 : vsm1;
        const size_t roff = (size_t)(kstart + t * TK) * (Dh / 4);

        // Prefetch next K into registers (latency hidden by S-gemm).
        if (pf) {
            #pragma unroll
            for (int i = 0; i < 4; i++) stk[i] = kp4[roff + sgm + i];
        }

        // ---- S = Q K^T ----
        // B frag (kc, nb): b0 = {K[8nb+g][16kc+2tig], +1}, b1 = d+8 -> non-trans ldmatrix.
        float sf[2][4][4];
        #pragma unroll
        for (int rb = 0; rb < 2; rb++)
            #pragma unroll
            for (int nb = 0; nb < 4; nb++)
                #pragma unroll
                for (int i = 0; i < 4; i++) sf[rb][nb][i] = 0.f;
        #pragma unroll
        for (int kc = 0; kc < 4; kc++) {
            #pragma unroll
            for (int p = 0; p < 2; p++) {   // p covers key-blocks {2p, 2p+1}
                uint32_t kf[4];
                const uint32_t a = ks + (uint32_t)((16 * p + kbase) * 128 + ((32 * kc + ksel) ^ kxor));
                ldsm4(kf, a);               // r0,r1 = b0,b1 of nb=2p; r2,r3 = nb=2p+1
                mmaf16(sf[0][2 * p],     qf[kc][0], kf);
                mmaf16(sf[1][2 * p],     qf[kc][1], kf);
                mmaf16(sf[0][2 * p + 1], qf[kc][0], kf + 2);
                mmaf16(sf[1][2 * p + 1], qf[kc][1], kf + 2);
            }
        }

        // ---- online softmax (R11 structure, unchanged) ----
        #pragma unroll
        for (int rb = 0; rb < 2; rb++) {
            float r0 = -1e30f, r1 = -1e30f;
            #pragma unroll
            for (int nb = 0; nb < 4; nb++) {
                r0 = fmaxf(r0, fmaxf(sf[rb][nb][0], sf[rb][nb][1]));
                r1 = fmaxf(r1, fmaxf(sf[rb][nb][2], sf[rb][nb][3]));
            }
            r0 = fmaxf(r0, __shfl_xor_sync(0xffffffffu, r0, 1));
            r0 = fmaxf(r0, __shfl_xor_sync(0xffffffffu, r0, 2));
            r1 = fmaxf(r1, __shfl_xor_sync(0xffffffffu, r1, 1));
            r1 = fmaxf(r1, __shfl_xor_sync(0xffffffffu, r1, 2));
            const float mn0 = fmaxf(mrow[rb][0], r0);
            const float mn1 = fmaxf(mrow[rb][1], r1);
            const float al0 = ex2f((mrow[rb][0] - mn0) * C);
            const float al1 = ex2f((mrow[rb][1] - mn1) * C);
            mrow[rb][0] = mn0; mrow[rb][1] = mn1;
            const float mb0 = mn0 * C, mb1 = mn1 * C;
            float s0 = 0.f, s1 = 0.f;
            #pragma unroll
            for (int nb = 0; nb < 4; nb++) {
                float p0 = ex2f(fmaf(sf[rb][nb][0], C, -mb0));
                float p1 = ex2f(fmaf(sf[rb][nb][1], C, -mb0));
                float p2 = ex2f(fmaf(sf[rb][nb][2], C, -mb1));
                float p3 = ex2f(fmaf(sf[rb][nb][3], C, -mb1));
                s0 += p0 + p1; s1 += p2 + p3;
                sf[rb][nb][0] = p0; sf[rb][nb][1] = p1;
                sf[rb][nb][2] = p2; sf[rb][nb][3] = p3;
            }
            s0 += __shfl_xor_sync(0xffffffffu, s0, 1);
            s0 += __shfl_xor_sync(0xffffffffu, s0, 2);
            s1 += __shfl_xor_sync(0xffffffffu, s1, 1);
            s1 += __shfl_xor_sync(0xffffffffu, s1, 2);
            lrow[rb][0] = lrow[rb][0] * al0 + s0;
            lrow[rb][1] = lrow[rb][1] * al1 + s1;
            #pragma unroll
            for (int nb = 0; nb < 8; nb++) {
                o[rb][nb][0] *= al0; o[rb][nb][1] *= al0;
                o[rb][nb][2] *= al1; o[rb][nb][3] *= al1;
            }
        }

        // Drain K prefetch into next buffer; prefetch next V.
        if (pf) {
            drain(stk, ksn);
            #pragma unroll
            for (int i = 0; i < 4; i++) stv[i] = vp4[roff + sgm + i];
        }

        // ---- O += P V ----
        // A frag (kc2): a0 = pack(c0,c1) of S-block 2kc2; a1 = pack(c2,c3); a2,a3 from
        // block 2kc2+1 — pure register pairing, no shuffles.
        // B frag (kc2, nb): b0 = {V[16kc2+2tig][8nb+g], V[16kc2+2tig+1][..]} -> ldmatrix.trans.
        #pragma unroll
        for (int kc2 = 0; kc2 < 2; kc2++) {
            uint32_t aP[2][4];
            #pragma unroll
            for (int rb = 0; rb < 2; rb++) {
                aP[rb][0] = packh(sf[rb][2 * kc2][0],     sf[rb][2 * kc2][1]);
                aP[rb][1] = packh(sf[rb][2 * kc2][2],     sf[rb][2 * kc2][3]);
                aP[rb][2] = packh(sf[rb][2 * kc2 + 1][0], sf[rb][2 * kc2 + 1][1]);
                aP[rb][3] = packh(sf[rb][2 * kc2 + 1][2], sf[rb][2 * kc2 + 1][3]);
            }
            #pragma unroll
            for (int nbp = 0; nbp < 4; nbp++) {   // covers d-blocks {2nbp, 2nbp+1}
                uint32_t vf[4];
                const uint32_t a = vs + (uint32_t)((16 * kc2 + vbase) * 128 + ((32 * nbp + vsel) ^ kxor));
                ldsm4t(vf, a);   // r0,r1 = b0,b1 of nb=2nbp; r2,r3 = nb=2nbp+1
                mmaf16(o[0][2 * nbp],     aP[0], vf);
                mmaf16(o[1][2 * nbp],     aP[1], vf);
                mmaf16(o[0][2 * nbp + 1], aP[0], vf + 2);
                mmaf16(o[1][2 * nbp + 1], aP[1], vf + 2);
            }
        }

        // Drain V prefetch, flip buffers.
        if (pf) {
            drain(stv, vsn);
            __syncthreads();
        }
    }

    // ---- normalize + store ----
    #pragma unroll
    for (int rb = 0; rb < 2; rb++) {
        const float inv0 = 1.f / lrow[rb][0];
        const float inv1 = 1.f / lrow[rb][1];
        const int row0 = qb * 128 + warp * 32 + rb * 16 + g;
        float* op0 = outg + ((size_t)bh * OUTROWS + row0) * Dh;
        float* op1 = op0 + 8 * Dh;
        #pragma unroll
        for (int nb = 0; nb < 8; nb++) {
            const int col = nb * 8 + 2 * tig;
            float2 v0 = { o[rb][nb][0] * inv0, o[rb][nb][1] * inv0 };
            *(float2*)(op0 + col) = v0;
            float2 v1 = { o[rb][nb][2] * inv1, o[rb][nb][3] * inv1 };
            *(float2*)(op1 + col) = v1;
        }
    }
}

extern "C" void kernel_launch(void* const* d_in, const int* in_sizes, int n_in,
                              void* d_out, int out_size)
{
    const float* q = (const float*)d_in[0];
    const float* k = (const float*)d_in[1];
    const float* v = (const float*)d_in[2];
    float* out = (float*)d_out;

    dim3 grid(62, 32);   // 62 q-blocks of 128 rows x 32 (b,h)
    swa_mma<<<grid, NT>>>(q, k, v, out);
}

// round 17
// speedup vs baseline: 1.2855x; 1.1499x over previous
#include <cuda_runtime.h>
#include <cstdint>

static constexpr int S_LEN   = 8192;
static constexpr int Dh      = 64;
static constexpr int OUTROWS = 7936;   // S - WINDOW/2
static constexpr int TK      = 32;     // keys per tile
static constexpr int NT      = 128;    // 4 warps x 32 q-rows, 2 CTAs/SM

__device__ __forceinline__ float ex2f(float x) {
    float r; asm("ex2.approx.ftz.f32 %0, %1;" : "=f"(r) : "f"(x)); return r;
}
// pack two f32 -> f16x2 (RN, unbiased): lo half = first arg.
__device__ __forceinline__ uint32_t packh(float lo, float hi) {
    uint32_t r; asm("cvt.rn.f16x2.f32 %0, %1, %2;" : "=r"(r) : "f"(hi), "f"(lo)); return r;
}
__device__ __forceinline__ void mmaf16(float d[4], const uint32_t a[4], const uint32_t* b) {
    asm("mma.sync.aligned.m16n8k16.row.col.f32.f16.f16.f32 "
        "{%0,%1,%2,%3}, {%4,%5,%6,%7}, {%8,%9}, {%0,%1,%2,%3};"
        : "+f"(d[0]), "+f"(d[1]), "+f"(d[2]), "+f"(d[3])
        : "r"(a[0]), "r"(a[1]), "r"(a[2]), "r"(a[3]), "r"(b[0]), "r"(b[1]));
}
__device__ __forceinline__ void ldsm4(uint32_t r[4], uint32_t saddr) {
    asm volatile("ldmatrix.sync.aligned.m8n8.x4.shared.b16 {%0,%1,%2,%3}, [%4];"
                 : "=r"(r[0]), "=r"(r[1]), "=r"(r[2]), "=r"(r[3]) : "r"(saddr));
}
__device__ __forceinline__ void ldsm4t(uint32_t r[4], uint32_t saddr) {
    asm volatile("ldmatrix.sync.aligned.m8n8.x4.trans.shared.b16 {%0,%1,%2,%3}, [%4];"
                 : "=r"(r[0]), "=r"(r[1]), "=r"(r[2]), "=r"(r[3]) : "r"(saddr));
}
__device__ __forceinline__ void sts128(uint32_t addr, uint32_t a, uint32_t b, uint32_t c, uint32_t d) {
    asm volatile("st.shared.v4.b32 [%0], {%1,%2,%3,%4};" :: "r"(addr), "r"(a), "r"(b), "r"(c), "r"(d));
}

__global__ __launch_bounds__(NT, 2)
void swa_mma(const float* __restrict__ qg, const float* __restrict__ kg,
             const float* __restrict__ vg, float* __restrict__ outg)
{
    // 4-buffer ring: tile t uses buf[t&3]; sync only after odd tiles.
    __shared__ __align__(16) char kbuf[4][TK * 128];   // 4 KB each, f16 [key][d], SW128
    __shared__ __align__(16) char vbuf[4][TK * 128];

    const int bh = blockIdx.y, qb = blockIdx.x;
    int kstart, klen;
    if (qb < 2) { kstart = 0; klen = 256; }
    else        { kstart = 256 + 512 * ((qb - 2) >> 2); klen = 512; }
    const int nt = 1 + klen / TK;   // tile 0 = 32 global keys, then window tiles

    const int tid  = threadIdx.x;
    const int warp = tid >> 5, lane = tid & 31;
    const int g = lane >> 2, tig = lane & 3;

    const float C = 0.125f * 1.44269504088896340736f;  // scale * log2(e)
    const size_t kvbase = (size_t)bh * S_LEN * Dh;

    // ldmatrix lane constants (identical to R14 winner).
    const int kxor  = (lane & 7) << 4;
    const int kbase = ((lane >> 4) << 3) + (lane & 7);
    const int ksel  = ((lane >> 3) & 1) << 4;
    const int vbase = (((lane >> 3) & 1) << 3) + (lane & 7);
    const int vsel  = ((lane >> 4) & 1) << 4;

    // Staging: thread -> key row skey, d-quad sq4 (16 f32 = 32 B f16).
    const int skey = tid >> 2, sq4 = tid & 3;
    const int sgm  = skey * 16 + sq4 * 4;
    const uint32_t sts0 = skey * 128 + ((sq4 * 32)      ^ ((skey & 7) << 4));
    const uint32_t sts1 = skey * 128 + ((sq4 * 32 + 16) ^ ((skey & 7) << 4));

    // ---- Q fragments (RN f16): qf[kc=4][rb=2][4] ----
    uint32_t qf[4][2][4];
    {
        const float* qp = qg + kvbase + (size_t)(qb * 128 + warp * 32) * Dh;
        #pragma unroll
        for (int kc = 0; kc < 4; kc++)
            #pragma unroll
            for (int rb = 0; rb < 2; rb++) {
                const int r0 = rb * 16 + g;
                const int c0 = kc * 16 + 2 * tig;
                qf[kc][rb][0] = packh(qp[(r0    ) * Dh + c0    ], qp[(r0    ) * Dh + c0 + 1]);
                qf[kc][rb][1] = packh(qp[(r0 + 8) * Dh + c0    ], qp[(r0 + 8) * Dh + c0 + 1]);
                qf[kc][rb][2] = packh(qp[(r0    ) * Dh + c0 + 8], qp[(r0    ) * Dh + c0 + 9]);
                qf[kc][rb][3] = packh(qp[(r0 + 8) * Dh + c0 + 8], qp[(r0 + 8) * Dh + c0 + 9]);
            }
    }

    float o[2][8][4];
    #pragma unroll
    for (int rb = 0; rb < 2; rb++)
        #pragma unroll
        for (int nb = 0; nb < 8; nb++)
            #pragma unroll
            for (int i = 0; i < 4; i++) o[rb][nb][i] = 0.f;
    float mrow[2][2] = {{-1e30f, -1e30f}, {-1e30f, -1e30f}};
    float lrow[2][2] = {{0.f, 0.f}, {0.f, 0.f}};

    const float4* kp4 = (const float4*)(kg + kvbase);
    const float4* vp4 = (const float4*)(vg + kvbase);
    float4 stk[4], stv[4];

    uint32_t kb[4], vb[4];
    #pragma unroll
    for (int i = 0; i < 4; i++) {
        kb[i] = (uint32_t)__cvta_generic_to_shared(kbuf[i]);
        vb[i] = (uint32_t)__cvta_generic_to_shared(vbuf[i]);
    }

    // Convert 4 staged float4 (16 f32) -> 8 f16x2 and store 32 B at sts0/sts1.
    auto drain = [&](const float4* st, uint32_t smbase) {
        uint32_t h[8];
        #pragma unroll
        for (int i = 0; i < 4; i++) {
            h[2 * i]     = packh(st[i].x, st[i].y);
            h[2 * i + 1] = packh(st[i].z, st[i].w);
        }
        sts128(smbase + sts0, h[0], h[1], h[2], h[3]);
        sts128(smbase + sts1, h[4], h[5], h[6], h[7]);
    };

    // Prologue: stage tiles 0 (global keys) and 1 (first window tile).
    {
        #pragma unroll
        for (int i = 0; i < 4; i++) { stk[i] = kp4[sgm + i]; stv[i] = vp4[sgm + i]; }
        drain(stk, kb[0]);
        drain(stv, vb[0]);
        const size_t r1 = (size_t)kstart * (Dh / 4);
        #pragma unroll
        for (int i = 0; i < 4; i++) { stk[i] = kp4[r1 + sgm + i]; stv[i] = vp4[r1 + sgm + i]; }
        drain(stk, kb[1]);
        drain(stv, vb[1]);
    }
    __syncthreads();

    for (int t = 0; t < nt; t++) {
        const uint32_t ks = kb[t & 3];
        const uint32_t vs = vb[t & 3];
        const bool pf = (t + 2) < nt;

        // Prefetch tile t+2 into registers (2-deep: drained at tile end).
        if (pf) {
            const size_t roff = (size_t)(kstart + (t + 1) * TK) * (Dh / 4);
            #pragma unroll
            for (int i = 0; i < 4; i++) { stk[i] = kp4[roff + sgm + i]; stv[i] = vp4[roff + sgm + i]; }
        }

        // ---- S = Q K^T ----
        float sf[2][4][4];
        #pragma unroll
        for (int rb = 0; rb < 2; rb++)
            #pragma unroll
            for (int nb = 0; nb < 4; nb++)
                #pragma unroll
                for (int i = 0; i < 4; i++) sf[rb][nb][i] = 0.f;
        #pragma unroll
        for (int kc = 0; kc < 4; kc++) {
            #pragma unroll
            for (int p = 0; p < 2; p++) {
                uint32_t kf[4];
                const uint32_t a = ks + (uint32_t)((16 * p + kbase) * 128 + ((32 * kc + ksel) ^ kxor));
                ldsm4(kf, a);
                mmaf16(sf[0][2 * p],     qf[kc][0], kf);
                mmaf16(sf[1][2 * p],     qf[kc][1], kf);
                mmaf16(sf[0][2 * p + 1], qf[kc][0], kf + 2);
                mmaf16(sf[1][2 * p + 1], qf[kc][1], kf + 2);
            }
        }

        // ---- online softmax (R14 structure, unchanged) ----
        #pragma unroll
        for (int rb = 0; rb < 2; rb++) {
            float r0 = -1e30f, r1 = -1e30f;
            #pragma unroll
            for (int nb = 0; nb < 4; nb++) {
                r0 = fmaxf(r0, fmaxf(sf[rb][nb][0], sf[rb][nb][1]));
                r1 = fmaxf(r1, fmaxf(sf[rb][nb][2], sf[rb][nb][3]));
            }
            r0 = fmaxf(r0, __shfl_xor_sync(0xffffffffu, r0, 1));
            r0 = fmaxf(r0, __shfl_xor_sync(0xffffffffu, r0, 2));
            r1 = fmaxf(r1, __shfl_xor_sync(0xffffffffu, r1, 1));
            r1 = fmaxf(r1, __shfl_xor_sync(0xffffffffu, r1, 2));
            const float mn0 = fmaxf(mrow[rb][0], r0);
            const float mn1 = fmaxf(mrow[rb][1], r1);
            const float al0 = ex2f((mrow[rb][0] - mn0) * C);
            const float al1 = ex2f((mrow[rb][1] - mn1) * C);
            mrow[rb][0] = mn0; mrow[rb][1] = mn1;
            const float mb0 = mn0 * C, mb1 = mn1 * C;
            float s0 = 0.f, s1 = 0.f;
            #pragma unroll
            for (int nb = 0; nb < 4; nb++) {
                float p0 = ex2f(fmaf(sf[rb][nb][0], C, -mb0));
                float p1 = ex2f(fmaf(sf[rb][nb][1], C, -mb0));
                float p2 = ex2f(fmaf(sf[rb][nb][2], C, -mb1));
                float p3 = ex2f(fmaf(sf[rb][nb][3], C, -mb1));
                s0 += p0 + p1; s1 += p2 + p3;
                sf[rb][nb][0] = p0; sf[rb][nb][1] = p1;
                sf[rb][nb][2] = p2; sf[rb][nb][3] = p3;
            }
            s0 += __shfl_xor_sync(0xffffffffu, s0, 1);
            s0 += __shfl_xor_sync(0xffffffffu, s0, 2);
            s1 += __shfl_xor_sync(0xffffffffu, s1, 1);
            s1 += __shfl_xor_sync(0xffffffffu, s1, 2);
            lrow[rb][0] = lrow[rb][0] * al0 + s0;
            lrow[rb][1] = lrow[rb][1] * al1 + s1;
            #pragma unroll
            for (int nb = 0; nb < 8; nb++) {
                o[rb][nb][0] *= al0; o[rb][nb][1] *= al0;
                o[rb][nb][2] *= al1; o[rb][nb][3] *= al1;
            }
        }

        // ---- O += P V ---- (P via register pairing; V via ldmatrix.trans)
        #pragma unroll
        for (int kc2 = 0; kc2 < 2; kc2++) {
            uint32_t aP[2][4];
            #pragma unroll
            for (int rb = 0; rb < 2; rb++) {
                aP[rb][0] = packh(sf[rb][2 * kc2][0],     sf[rb][2 * kc2][1]);
                aP[rb][1] = packh(sf[rb][2 * kc2][2],     sf[rb][2 * kc2][3]);
                aP[rb][2] = packh(sf[rb][2 * kc2 + 1][0], sf[rb][2 * kc2 + 1][1]);
                aP[rb][3] = packh(sf[rb][2 * kc2 + 1][2], sf[rb][2 * kc2 + 1][3]);
            }
            #pragma unroll
            for (int nbp = 0; nbp < 4; nbp++) {
                uint32_t vf[4];
                const uint32_t a = vs + (uint32_t)((16 * kc2 + vbase) * 128 + ((32 * nbp + vsel) ^ kxor));
                ldsm4t(vf, a);
                mmaf16(o[0][2 * nbp],     aP[0], vf);
                mmaf16(o[1][2 * nbp],     aP[1], vf);
                mmaf16(o[0][2 * nbp + 1], aP[0], vf + 2);
                mmaf16(o[1][2 * nbp + 1], aP[1], vf + 2);
            }
        }

        // Drain the t+2 prefetch into its ring slot (off the softmax->PV chain).
        if (pf) {
            drain(stk, kb[(t + 2) & 3]);
            drain(stv, vb[(t + 2) & 3]);
        }
        // Sync only every second tile: warps get a 2-tile slack window.
        if (t & 1) __syncthreads();
    }

    // ---- normalize + store ----
    #pragma unroll
    for (int rb = 0; rb < 2; rb++) {
        const float inv0 = 1.f / lrow[rb][0];
        const float inv1 = 1.f / lrow[rb][1];
        const int row0 = qb * 128 + warp * 32 + rb * 16 + g;
        float* op0 = outg + ((size_t)bh * OUTROWS + row0) * Dh;
        float* op1 = op0 + 8 * Dh;
        #pragma unroll
        for (int nb = 0; nb < 8; nb++) {
            const int col = nb * 8 + 2 * tig;
            float2 v0 = { o[rb][nb][0] * inv0, o[rb][nb][1] * inv0 };
            *(float2*)(op0 + col) = v0;
            float2 v1 = { o[rb][nb][2] * inv1, o[rb][nb][3] * inv1 };
            *(float2*)(op1 + col) = v1;
        }
    }
}

extern "C" void kernel_launch(void* const* d_in, const int* in_sizes, int n_in,
                              void* d_out, int out_size)
{
    const float* q = (const float*)d_in[0];
    const float* k = (const float*)d_in[1];
    const float* v = (const float*)d_in[2];
    float* out = (float*)d_out;

    dim3 grid(62, 32);   // 62 q-blocks of 128 rows x 32 (b,h)
    swa_mma<<<grid, NT>>>(q, k, v, out);
}